// round 13
// baseline (speedup 1.0000x reference)
#include <cuda_runtime.h>

// ---------------- Problem constants ----------------
#define NBOX 8000          // 5 anchors * 40 * 40
#define HW 40
#define NCLS 20
#define CHSTRIDE (HW*HW)   // 1600 floats between channels
#define STRIDEPX 8.0f      // 320 / 40

#define GBLK 64            // persistent grid (co-resident on 148 SMs)
#define TBLK 512
#define JC 4               // rank j-chunks
#define CSMAX 2000         // ceil(8000/4)

#define MMASK 256          // mask-matrix fast-path capacity (expected M ~ 200)
#define NW 8               // 256/32
#define CAP2 1024          // per-class precomputed-slot capacity (mid path)

// ---------------- Scratch (device globals, no allocation) ----------------
__device__ float              d_dec6[NBOX * 6];
__device__ unsigned long long d_vkey[NBOX];
__device__ unsigned char      d_vcode[NBOX];
__device__ int                d_nv;                  // valid count (reset in-kernel each launch)
__device__ unsigned           d_partial[JC * NBOX];  // packed: rank | cls_rank<<16
__device__ int                d_cnt[NCLS];
__device__ float4             d_cg4 [NCLS * CAP2];
__device__ float              d_car [NCLS * CAP2];
__device__ int                d_cr  [NCLS * CAP2];
__device__ float              d_crow6[NCLS * CAP2 * 6];
__device__ int                d_cand[NCLS * NBOX];   // fallback only: r | orig<<16
__device__ unsigned           d_barc;                // grid-barrier arrive count
__device__ volatile unsigned  d_barg;                // grid-barrier generation (monotonic)

// software grid barrier: safe across graph replays (count returns to 0, gen grows)
__device__ __forceinline__ void grid_sync() {
    __syncthreads();
    if (threadIdx.x == 0) {
        __threadfence();
        unsigned g = d_barg;
        if (atomicAdd(&d_barc, 1u) == gridDim.x - 1) {
            d_barc = 0;
            __threadfence();
            d_barg = g + 1;
        } else {
            while (d_barg == g) __nanosleep(32);
            __threadfence();
        }
    }
    __syncthreads();
}

// IoU >= 0.5 <=> 2*inter >= union (division-free)
__device__ __forceinline__ bool sup_test(float xi1, float yi1, float xi2, float yi2, float ai,
                                         float xj1, float yj1, float xj2, float yj2, float aj) {
    float iw = fmaxf(fminf(xi2, xj2) - fmaxf(xi1, xj1), 0.0f);
    float ih = fmaxf(fminf(yi2, yj2) - fmaxf(yi1, yj1), 0.0f);
    float inter = iw * ih;
    float denom = ai + aj - inter + 1e-6f;
    return 2.0f * inter >= denom;
}

__global__ __launch_bounds__(TBLK, 1)
void k_all(const float* __restrict__ x, const float* __restrict__ anchors,
           float* __restrict__ out) {
    // phase-aliased shared buffer:
    //  rank: sk (16000B ull keys) @0, sc (2000B codes) @16000
    //  nms:  sx1@0 sy1@4096 sx2@8192 sy2@12288 sar@16384 sr@20480 smask@24576 (8192B)
    __shared__ __align__(16) unsigned char sbuf[32768];
    __shared__ unsigned srow[NW], skw[NW];

    int tid = threadIdx.x;
    int b   = blockIdx.x;
    int gid = b * TBLK + tid;

    // ================= P1: decode + valid append + zero out/counters =================
    for (int k = gid; k < NBOX * 6; k += GBLK * TBLK) out[k] = 0.0f;
    if (gid < NCLS) d_cnt[gid] = 0;

    if (gid < NBOX) {
        int i   = gid;
        int a   = i / (HW * HW);
        int rem = i - a * (HW * HW);
        int gy  = rem / HW;
        int gx  = rem - gy * HW;
        int base = ((a * 25) * HW + gy) * HW + gx;

        float t[5];
#pragma unroll
        for (int k = 0; k < 5; k++) t[k] = x[base + k * CHSTRIDE];
        float cl[NCLS];
#pragma unroll
        for (int c = 0; c < NCLS; c++) cl[c] = x[base + (5 + c) * CHSTRIDE];

        float tx   = 1.0f / (1.0f + expf(-t[0]));
        float ty   = 1.0f / (1.0f + expf(-t[1]));
        float conf = 1.0f / (1.0f + expf(-t[4]));
        float aw = anchors[a * 2 + 0];
        float ah = anchors[a * 2 + 1];
        float bx = (tx + (float)gx) * STRIDEPX;
        float by = (ty + (float)gy) * STRIDEPX;
        float bw = expf(t[2]) * aw * STRIDEPX;
        float bh = expf(t[3]) * ah * STRIDEPX;

        float best = cl[0];
        int bc = 0;
#pragma unroll
        for (int c = 1; c < NCLS; c++)
            if (cl[c] > best) { best = cl[c]; bc = c; }

        d_dec6[i * 6 + 0] = bx;
        d_dec6[i * 6 + 1] = by;
        d_dec6[i * 6 + 2] = bw;
        d_dec6[i * 6 + 3] = bh;
        d_dec6[i * 6 + 4] = conf;
        d_dec6[i * 6 + 5] = (float)bc;

        // valid (conf>0.5 <=> logit>0): append; slot order nondeterministic but
        // ranks are value-based -> deterministic output.
        if (t[4] > 0.0f) {
            int slot = atomicAdd(&d_nv, 1);
            unsigned u = __float_as_uint(conf);
            d_vkey[slot]  = ((unsigned long long)(~u) << 32) | (unsigned long long)(unsigned)i;
            d_vcode[slot] = (unsigned char)bc;
        }
    }
    grid_sync();

    // ================= P2: chunked rank (global + same-class, packed) ================
    {
        unsigned long long* sk = (unsigned long long*)sbuf;
        unsigned char*      sc = sbuf + 16000;
        int NV = d_nv;
        int CS = (NV + JC - 1) / JC;     // <= 2000
        int g   = b >> 2;                // i-group 0..15 (16*512 = 8192 >= NV)
        int cch = b & 3;                 // j-chunk 0..3
        int j0 = cch * CS;
        int cnt = NV - j0; if (cnt > CS) cnt = CS; if (cnt < 0) cnt = 0;
        for (int t = tid; t < cnt; t += TBLK) {
            sk[t] = d_vkey[j0 + t];
            sc[t] = d_vcode[j0 + t];
        }
        __syncthreads();
        int i = g * TBLK + tid;
        if (i < NV) {
            unsigned long long my = d_vkey[i];
            unsigned char myc = d_vcode[i];
            unsigned acc = 0;
#pragma unroll 8
            for (int j = 0; j < cnt; j++) {
                bool lt = sk[j] < my;
                acc += lt ? (1u + (((sc[j] == myc) ? 1u : 0u) << 16)) : 0u;
            }
            d_partial[cch * NBOX + i] = acc;
        }
    }
    grid_sync();

    // ================= P3: scatter -> per-class precomputed slots =====================
    {
        int NV = d_nv;
        for (int i = gid; i < NV; i += GBLK * TBLK) {
            unsigned s = d_partial[0 * NBOX + i] + d_partial[1 * NBOX + i]
                       + d_partial[2 * NBOX + i] + d_partial[3 * NBOX + i];
            int r  = (int)(s & 0xffffu);
            int rc = (int)(s >> 16);
            unsigned long long key = d_vkey[i];
            int orig = (int)(unsigned)(key & 0xffffffffu);
            int cls  = (int)d_vcode[i];
            atomicAdd(&d_cnt[cls], 1);
            d_cand[cls * NBOX + rc] = r | (orig << 16);   // fallback path
            if (rc < CAP2) {
                float cx = d_dec6[orig * 6 + 0];
                float cy = d_dec6[orig * 6 + 1];
                float w  = d_dec6[orig * 6 + 2];
                float h  = d_dec6[orig * 6 + 3];
                float x1 = cx - 0.5f * w, y1 = cy - 0.5f * h;
                float x2 = cx + 0.5f * w, y2 = cy + 0.5f * h;
                int slot = cls * CAP2 + rc;
                d_cg4[slot] = make_float4(x1, y1, x2, y2);
                d_car[slot] = fabsf((x2 - x1) * (y2 - y1));
                d_cr [slot] = r;
                d_crow6[slot * 6 + 0] = cx;
                d_crow6[slot * 6 + 1] = cy;
                d_crow6[slot * 6 + 2] = w;
                d_crow6[slot * 6 + 3] = h;
                d_crow6[slot * 6 + 4] = d_dec6[orig * 6 + 4];
                d_crow6[slot * 6 + 5] = d_dec6[orig * 6 + 5];
            }
        }
    }
    grid_sync();

    // ================= P4: per-class NMS (blocks 0..19) ==============================
    if (b == 20 && tid == 0) d_nv = 0;   // reset accumulator for next graph replay
    int c = b;
    if (c >= NCLS) return;

    float*    sx1 = (float*)(sbuf);
    float*    sy1 = (float*)(sbuf + 4096);
    float*    sx2 = (float*)(sbuf + 8192);
    float*    sy2 = (float*)(sbuf + 12288);
    float*    sar = (float*)(sbuf + 16384);
    int*      sr  = (int*)  (sbuf + 20480);
    unsigned* smask = (unsigned*)(sbuf + 24576);

    int lane = tid & 31;
    int warp = tid >> 5;
    if (tid < NW) srow[tid] = 0;

    int M = d_cnt[c];
    if (M == 0) return;

    if (M <= CAP2) {
        for (int t = tid; t < M; t += TBLK) {
            float4 g = d_cg4[c * CAP2 + t];
            sx1[t] = g.x; sy1[t] = g.y; sx2[t] = g.z; sy2[t] = g.w;
            sar[t] = d_car[c * CAP2 + t];
            sr [t] = d_cr [c * CAP2 + t];
        }
        __syncthreads();

        if (M <= MMASK) {
            // ---- ballot mask fill: one warp per row ----
            int nw = (M + 31) >> 5;
            for (int i = warp; i < M; i += 16) {
                float xi1 = sx1[i], yi1 = sy1[i], xi2 = sx2[i], yi2 = sy2[i], ai = sar[i];
                int wq0 = (i + 1) >> 5;
                unsigned rowany = 0;
                if (lane == 0)
                    for (int q = 0; q < wq0; q++) smask[i * NW + q] = 0;
                for (int wq = wq0; wq < nw; wq++) {
                    int j = (wq << 5) + lane;
                    bool s = (j > i) && (j < M) &&
                             sup_test(xi1, yi1, xi2, yi2, ai,
                                      sx1[j], sy1[j], sx2[j], sy2[j], sar[j]);
                    unsigned bits = __ballot_sync(0xffffffffu, s);
                    if (lane == 0) smask[i * NW + wq] = bits;
                    rowany |= bits;
                }
                if (lane == 0 && rowany) atomicOr(&srow[i >> 5], 1u << (i & 31));
            }
            __syncthreads();

            // ---- two-level sweep (warp 0): intra-word serial, cross-word parallel ----
            if (tid < 32) {
                unsigned kwq = 0;
                if (lane < NW) {
                    int lo = lane * 32;
                    if (lo < M) {
                        int rem = M - lo;
                        kwq = (rem >= 32) ? 0xffffffffu : ((1u << rem) - 1u);
                    }
                }
                int nwl = (M + 31) >> 5;
                for (int w = 0; w < nwl; w++) {
                    unsigned kwv = __shfl_sync(0xffffffffu, kwq, w);
                    unsigned rw  = srow[w];
                    unsigned active = kwv & rw;
                    while (active) {           // uniform across lanes (same data)
                        int bb = __ffs(active) - 1;
                        unsigned row_w = smask[(w * 32 + bb) * NW + w];  // broadcast LDS
                        kwv &= ~row_w;                    // clears only bits > bb in word w
                        active = kwv & rw & (0xfffffffeu << bb);
                    }
                    if (lane == w) kwq = kwv;
                    // bulk apply this word's surviving suppressors to later words
                    unsigned contrib = kwv & rw;
                    if (lane > w && lane < NW) {
                        unsigned acc = 0, cc = contrib;
                        while (cc) {                       // independent pipelined LDS
                            int bb = __ffs(cc) - 1; cc &= cc - 1;
                            acc |= smask[(w * 32 + bb) * NW + lane];
                        }
                        kwq &= ~acc;
                    }
                }
                if (lane < NW) skw[lane] = kwq;
            }
            __syncthreads();
            for (int t = tid; t < M; t += TBLK) {
                if ((skw[t >> 5] >> (t & 31)) & 1u) {
                    int r = sr[t];
                    int slot = c * CAP2 + t;
#pragma unroll
                    for (int q = 0; q < 6; q++) out[6 * r + q] = d_crow6[slot * 6 + q];
                }
            }
        } else {
            // ---- mid path (MMASK < M <= CAP2): pivot loop ----
            unsigned char* skbyte = (unsigned char*)smask;   // 8192B >= CAP2
            for (int t = tid; t < M; t += TBLK) skbyte[t] = 1;
            __syncthreads();
            for (int i = 0; i < M - 1; i++) {
                __syncthreads();
                if (!skbyte[i]) continue;
                float xi1 = sx1[i], yi1 = sy1[i], xi2 = sx2[i], yi2 = sy2[i], ai = sar[i];
                for (int j = i + 1 + tid; j < M; j += TBLK) {
                    if (!skbyte[j]) continue;
                    if (sup_test(xi1, yi1, xi2, yi2, ai,
                                 sx1[j], sy1[j], sx2[j], sy2[j], sar[j]))
                        skbyte[j] = 0;
                }
            }
            __syncthreads();
            for (int t = tid; t < M; t += TBLK) {
                if (skbyte[t]) {
                    int r = sr[t];
                    int slot = c * CAP2 + t;
#pragma unroll
                    for (int q = 0; q < 6; q++) out[6 * r + q] = d_crow6[slot * 6 + q];
                }
            }
        }
    } else {
        // ---- fallback (M > CAP2, never expected): global pivot loop via d_cand ----
        unsigned char* skbyte = (unsigned char*)sbuf;      // 32768B >= 8000 >= M
        for (int t = tid; t < M; t += TBLK) skbyte[t] = 1;
        __syncthreads();
        for (int i = 0; i < M - 1; i++) {
            __syncthreads();
            if (!skbyte[i]) continue;
            int oi = d_cand[c * NBOX + i] >> 16;
            float cx = d_dec6[oi * 6 + 0], cy = d_dec6[oi * 6 + 1];
            float w  = d_dec6[oi * 6 + 2], h  = d_dec6[oi * 6 + 3];
            float xi1 = cx - 0.5f * w, yi1 = cy - 0.5f * h;
            float xi2 = cx + 0.5f * w, yi2 = cy + 0.5f * h;
            float ai = fabsf((xi2 - xi1) * (yi2 - yi1));
            for (int j = i + 1 + tid; j < M; j += TBLK) {
                if (!skbyte[j]) continue;
                int oj = d_cand[c * NBOX + j] >> 16;
                float cxj = d_dec6[oj * 6 + 0], cyj = d_dec6[oj * 6 + 1];
                float wj  = d_dec6[oj * 6 + 2], hj  = d_dec6[oj * 6 + 3];
                float xj1 = cxj - 0.5f * wj, yj1 = cyj - 0.5f * hj;
                float xj2 = cxj + 0.5f * wj, yj2 = cyj + 0.5f * hj;
                float aj = fabsf((xj2 - xj1) * (yj2 - yj1));
                if (sup_test(xi1, yi1, xi2, yi2, ai, xj1, yj1, xj2, yj2, aj))
                    skbyte[j] = 0;
            }
        }
        __syncthreads();
        for (int t = tid; t < M; t += TBLK) {
            if (skbyte[t]) {
                int p = d_cand[c * NBOX + t];
                int r = p & 0xffff, orig = p >> 16;
#pragma unroll
                for (int q = 0; q < 6; q++) out[6 * r + q] = d_dec6[orig * 6 + q];
            }
        }
    }
}

// ---------------- launch ----------------
extern "C" void kernel_launch(void* const* d_in, const int* in_sizes, int n_in,
                              void* d_out, int out_size) {
    const float* x;
    const float* anchors;
    if (in_sizes[0] == 10) { anchors = (const float*)d_in[0]; x = (const float*)d_in[1]; }
    else                   { x = (const float*)d_in[0]; anchors = (const float*)d_in[1]; }
    float* out = (float*)d_out;

    k_all<<<GBLK, TBLK>>>(x, anchors, out);
}

// round 14
// speedup vs baseline: 1.7251x; 1.7251x over previous
#include <cuda_runtime.h>

// ---------------- Problem constants ----------------
#define NBOX 8000          // 5 anchors * 40 * 40
#define HW 40
#define NCLS 20
#define CHSTRIDE (HW*HW)   // 1600 floats between channels
#define STRIDEPX 8.0f      // 320 / 40

#define JC 16
#define CHUNKMAX 500       // ceil(8000/16)
#define IGROUPS 32         // 32*256 = 8192 >= NV

#define MMASK 256          // mask-matrix fast-path capacity (expected M ~ 200)
#define NW 8               // 256/32
#define CAP2 1024          // per-class precomputed-slot capacity (mid path)

// ---------------- Scratch (device globals, no allocation) ----------------
__device__ float              d_dec6[NBOX * 6];      // decoded rows, original index order
__device__ unsigned long long d_vkey[NBOX];          // valid keys: (~bits(conf))<<32 | idx
__device__ unsigned char      d_vcode[NBOX];         // valid class
__device__ int                d_nv;                  // valid count accumulator
__device__ int                d_nv2;                 // snapshot (set by k_rank)
__device__ unsigned           d_partial[JC * NBOX];  // packed: rank | cls_rank<<16
__device__ int                d_cnt[NCLS];           // per-class candidate count
__device__ float4             d_cg4 [NCLS * CAP2];   // slot (cls,rc): x1,y1,x2,y2
__device__ float              d_car [NCLS * CAP2];   // slot: area
__device__ int                d_cr  [NCLS * CAP2];   // slot: output row (global rank)
__device__ float              d_crow6[NCLS * CAP2 * 6]; // slot: full output row
__device__ int                d_cand[NCLS * NBOX];   // fallback only: r | orig<<16

// ---------------- K1: decode + valid append + zero output/counters ----------------
__global__ void k_decode(const float* __restrict__ x, const float* __restrict__ anchors,
                         float* __restrict__ out) {
    int tid = threadIdx.x;
    int gid = blockIdx.x * 256 + tid;

    // zero output (poisoned before timing) and class counters
    for (int k = gid; k < NBOX * 6; k += 32 * 256) out[k] = 0.0f;
    if (gid < NCLS) d_cnt[gid] = 0;

    int  i   = gid;
    bool inb = (i < NBOX);
    int  ii  = inb ? i : 0;    // clamp for safe loads

    int a   = ii / (HW * HW);
    int rem = ii - a * (HW * HW);
    int gy  = rem / HW;
    int gx  = rem - gy * HW;
    int base = ((a * 25) * HW + gy) * HW + gx;

    // hoist all 25 loads (max MLP)
    float t[5];
#pragma unroll
    for (int k = 0; k < 5; k++) t[k] = x[base + k * CHSTRIDE];
    float cl[NCLS];
#pragma unroll
    for (int c = 0; c < NCLS; c++) cl[c] = x[base + (5 + c) * CHSTRIDE];

    float tx   = 1.0f / (1.0f + expf(-t[0]));
    float ty   = 1.0f / (1.0f + expf(-t[1]));
    float conf = 1.0f / (1.0f + expf(-t[4]));

    float aw = anchors[a * 2 + 0];
    float ah = anchors[a * 2 + 1];

    float bx = (tx + (float)gx) * STRIDEPX;
    float by = (ty + (float)gy) * STRIDEPX;
    float bw = expf(t[2]) * aw * STRIDEPX;
    float bh = expf(t[3]) * ah * STRIDEPX;

    // argmax (strict '>' keeps first occurrence like jnp.argmax)
    float best = cl[0];
    int bc = 0;
#pragma unroll
    for (int c = 1; c < NCLS; c++)
        if (cl[c] > best) { best = cl[c]; bc = c; }

    if (!inb) return;

    d_dec6[i * 6 + 0] = bx;
    d_dec6[i * 6 + 1] = by;
    d_dec6[i * 6 + 2] = bw;
    d_dec6[i * 6 + 3] = bh;
    d_dec6[i * 6 + 4] = conf;
    d_dec6[i * 6 + 5] = (float)bc;

    // valid (conf > 0.5 <=> logit > 0): contiguous append.
    // Slot order nondeterministic; ranks are value-based -> deterministic output.
    if (t[4] > 0.0f) {
        int slot = atomicAdd(&d_nv, 1);
        unsigned u = __float_as_uint(conf);     // conf in (0,1): bits monotone
        d_vkey[slot]  = ((unsigned long long)(~u) << 32) | (unsigned long long)(unsigned)i;
        d_vcode[slot] = (unsigned char)bc;
    }
}

// ---------------- K2: chunked rank over valid boxes (+ snapshot NV) ----------------
__global__ void k_rank() {
    __shared__ unsigned long long sk[CHUNKMAX];
    __shared__ unsigned char     sc[CHUNKMAX];
    int NV = d_nv;
    if (blockIdx.x == 0 && threadIdx.x == 0) d_nv2 = NV;
    int CS = (NV + JC - 1) / JC;
    int g = blockIdx.x / JC;
    int c = blockIdx.x - g * JC;
    int j0 = c * CS;
    int cnt = NV - j0; if (cnt > CS) cnt = CS; if (cnt < 0) cnt = 0;
    for (int t = threadIdx.x; t < cnt; t += 256) {
        sk[t] = d_vkey[j0 + t];
        sc[t] = d_vcode[j0 + t];
    }
    __syncthreads();
    int i = g * 256 + threadIdx.x;
    if (i < NV) {
        unsigned long long my = d_vkey[i];
        unsigned char myc = d_vcode[i];
        unsigned acc = 0;
#pragma unroll 8
        for (int j = 0; j < cnt; j++) {
            bool lt = sk[j] < my;
            acc += lt ? (1u + (((sc[j] == myc) ? 1u : 0u) << 16)) : 0u;
        }
        d_partial[c * NBOX + i] = acc;
    }
}

// ---------------- K2b: scatter -> per-class precomputed slots ----------------
__global__ void k_scatter() {
    int i = blockIdx.x * 256 + threadIdx.x;
    int NV = d_nv;
    if (i >= NV) return;
    unsigned s = 0;
#pragma unroll
    for (int c = 0; c < JC; c++) s += d_partial[c * NBOX + i];
    int r  = (int)(s & 0xffffu);   // global rank among valid == output row
    int rc = (int)(s >> 16);       // class rank (unique within class)
    unsigned long long key = d_vkey[i];
    int orig = (int)(unsigned)(key & 0xffffffffu);
    int cls  = (int)d_vcode[i];
    atomicAdd(&d_cnt[cls], 1);
    if (rc < NBOX) d_cand[cls * NBOX + rc] = r | (orig << 16);  // fallback path
    if (rc < CAP2) {
        float cx = d_dec6[orig * 6 + 0];
        float cy = d_dec6[orig * 6 + 1];
        float w  = d_dec6[orig * 6 + 2];
        float h  = d_dec6[orig * 6 + 3];
        float x1 = cx - 0.5f * w, y1 = cy - 0.5f * h;
        float x2 = cx + 0.5f * w, y2 = cy + 0.5f * h;
        int slot = cls * CAP2 + rc;
        d_cg4[slot] = make_float4(x1, y1, x2, y2);
        d_car[slot] = fabsf((x2 - x1) * (y2 - y1));
        d_cr [slot] = r;
        d_crow6[slot * 6 + 0] = cx;
        d_crow6[slot * 6 + 1] = cy;
        d_crow6[slot * 6 + 2] = w;
        d_crow6[slot * 6 + 3] = h;
        d_crow6[slot * 6 + 4] = d_dec6[orig * 6 + 4];
        d_crow6[slot * 6 + 5] = d_dec6[orig * 6 + 5];
    }
}

// IoU >= 0.5 <=> 2*inter >= union (division-free)
__device__ __forceinline__ bool sup_test(float xi1, float yi1, float xi2, float yi2, float ai,
                                         float xj1, float yj1, float xj2, float yj2, float aj) {
    float iw = fmaxf(fminf(xi2, xj2) - fmaxf(xi1, xj1), 0.0f);
    float ih = fmaxf(fminf(yi2, yj2) - fmaxf(yi1, yj1), 0.0f);
    float inter = iw * ih;
    float denom = ai + aj - inter + 1e-6f;
    return 2.0f * inter >= denom;
}

// ---------------- K3: per-class NMS (pure: load -> fill -> sweep -> emit) ----------------
__global__ void k_nms(float* __restrict__ out) {
    __shared__ float    sx1[CAP2], sy1[CAP2], sx2[CAP2], sy2[CAP2], sar[CAP2];
    __shared__ int      sr[CAP2];
    __shared__ unsigned smask[MMASK * NW];
    __shared__ unsigned srow[NW], skw[NW];

    int c    = blockIdx.x;
    int tid  = threadIdx.x;
    int lane = tid & 31;
    int warp = tid >> 5;

    if (c == 0 && tid == 0) d_nv = 0;   // reset accumulator for next graph replay
    if (tid < NW) srow[tid] = 0;

    int M = d_cnt[c];
    if (M == 0) return;

    if (M <= CAP2) {
        // ---- coalesced load of precomputed per-class slots ----
        for (int t = tid; t < M; t += 512) {
            float4 g = d_cg4[c * CAP2 + t];
            sx1[t] = g.x; sy1[t] = g.y; sx2[t] = g.z; sy2[t] = g.w;
            sar[t] = d_car[c * CAP2 + t];
            sr [t] = d_cr [c * CAP2 + t];
        }
        __syncthreads();

        if (M <= MMASK) {
            // ---- ballot mask fill: one warp per row ----
            int nw = (M + 31) >> 5;
            for (int i = warp; i < M; i += 16) {
                float xi1 = sx1[i], yi1 = sy1[i], xi2 = sx2[i], yi2 = sy2[i], ai = sar[i];
                int wq0 = (i + 1) >> 5;
                unsigned rowany = 0;
                if (lane == 0)
                    for (int q = 0; q < wq0; q++) smask[i * NW + q] = 0;
                for (int wq = wq0; wq < nw; wq++) {
                    int j = (wq << 5) + lane;
                    bool s = (j > i) && (j < M) &&
                             sup_test(xi1, yi1, xi2, yi2, ai,
                                      sx1[j], sy1[j], sx2[j], sy2[j], sar[j]);
                    unsigned bits = __ballot_sync(0xffffffffu, s);
                    if (lane == 0) smask[i * NW + wq] = bits;
                    rowany |= bits;
                }
                if (lane == 0 && rowany) atomicOr(&srow[i >> 5], 1u << (i & 31));
            }
            __syncthreads();

            // ---- two-level sweep (warp 0): intra-word serial chain, cross-word parallel ----
            if (tid < 32) {
                unsigned kwq = 0;                      // lane q holds keep-word q
                if (lane < NW) {
                    int lo = lane * 32;
                    if (lo < M) {
                        int rem = M - lo;
                        kwq = (rem >= 32) ? 0xffffffffu : ((1u << rem) - 1u);
                    }
                }
                int nwl = (M + 31) >> 5;
                for (int w = 0; w < nwl; w++) {
                    unsigned kwv = __shfl_sync(0xffffffffu, kwq, w);  // word w, uniform
                    unsigned rw  = srow[w];
                    unsigned active = kwv & rw;
                    while (active) {                   // short chain: 1 LDS per step
                        int bb = __ffs(active) - 1;
                        unsigned row_w = smask[(w * 32 + bb) * NW + w];  // broadcast LDS
                        kwv &= ~row_w;                 // mask rows hold only j>i bits
                        active = kwv & rw & (0xfffffffeu << bb);
                    }
                    if (lane == w) kwq = kwv;
                    // bulk-apply word w's surviving suppressors to later words (parallel lanes)
                    unsigned contrib = kwv & rw;
                    if (lane > w && lane < NW) {
                        unsigned acc = 0, cc = contrib;
                        while (cc) {                   // independent pipelined LDS
                            int bb = __ffs(cc) - 1; cc &= cc - 1;
                            acc |= smask[(w * 32 + bb) * NW + lane];
                        }
                        kwq &= ~acc;
                    }
                }
                if (lane < NW) skw[lane] = kwq;
            }
            __syncthreads();
            // ---- emit kept rows from precomputed row data ----
            for (int t = tid; t < M; t += 512) {
                if ((skw[t >> 5] >> (t & 31)) & 1u) {
                    int r = sr[t];
                    int slot = c * CAP2 + t;
#pragma unroll
                    for (int q = 0; q < 6; q++) out[6 * r + q] = d_crow6[slot * 6 + q];
                }
            }
        } else {
            // ---- mid path (MMASK < M <= CAP2): pivot loop ----
            unsigned char* skbyte = (unsigned char*)smask;   // 8192B >= CAP2
            for (int t = tid; t < M; t += 512) skbyte[t] = 1;
            __syncthreads();
            for (int i = 0; i < M - 1; i++) {
                __syncthreads();
                if (!skbyte[i]) continue;
                float xi1 = sx1[i], yi1 = sy1[i], xi2 = sx2[i], yi2 = sy2[i], ai = sar[i];
                for (int j = i + 1 + tid; j < M; j += 512) {
                    if (!skbyte[j]) continue;
                    if (sup_test(xi1, yi1, xi2, yi2, ai,
                                 sx1[j], sy1[j], sx2[j], sy2[j], sar[j]))
                        skbyte[j] = 0;
                }
            }
            __syncthreads();
            for (int t = tid; t < M; t += 512) {
                if (skbyte[t]) {
                    int r = sr[t];
                    int slot = c * CAP2 + t;
#pragma unroll
                    for (int q = 0; q < 6; q++) out[6 * r + q] = d_crow6[slot * 6 + q];
                }
            }
        }
    } else {
        // ---- fallback (M > CAP2, never expected): global pivot loop via d_cand ----
        unsigned char* skbyte = (unsigned char*)sx1;     // sx1..sar span 20KB >= 8000
        for (int t = tid; t < M; t += 512) skbyte[t] = 1;
        __syncthreads();
        for (int i = 0; i < M - 1; i++) {
            __syncthreads();
            if (!skbyte[i]) continue;
            int oi = d_cand[c * NBOX + i] >> 16;
            float cx = d_dec6[oi * 6 + 0], cy = d_dec6[oi * 6 + 1];
            float w  = d_dec6[oi * 6 + 2], h  = d_dec6[oi * 6 + 3];
            float xi1 = cx - 0.5f * w, yi1 = cy - 0.5f * h;
            float xi2 = cx + 0.5f * w, yi2 = cy + 0.5f * h;
            float ai = fabsf((xi2 - xi1) * (yi2 - yi1));
            for (int j = i + 1 + tid; j < M; j += 512) {
                if (!skbyte[j]) continue;
                int oj = d_cand[c * NBOX + j] >> 16;
                float cxj = d_dec6[oj * 6 + 0], cyj = d_dec6[oj * 6 + 1];
                float wj  = d_dec6[oj * 6 + 2], hj  = d_dec6[oj * 6 + 3];
                float xj1 = cxj - 0.5f * wj, yj1 = cyj - 0.5f * hj;
                float xj2 = cxj + 0.5f * wj, yj2 = cyj + 0.5f * hj;
                float aj = fabsf((xj2 - xj1) * (yj2 - yj1));
                if (sup_test(xi1, yi1, xi2, yi2, ai, xj1, yj1, xj2, yj2, aj))
                    skbyte[j] = 0;
            }
        }
        __syncthreads();
        for (int t = tid; t < M; t += 512) {
            if (skbyte[t]) {
                int p = d_cand[c * NBOX + t];
                int r = p & 0xffff, orig = p >> 16;
#pragma unroll
                for (int q = 0; q < 6; q++) out[6 * r + q] = d_dec6[orig * 6 + q];
            }
        }
    }
}

// ---------------- launch ----------------
extern "C" void kernel_launch(void* const* d_in, const int* in_sizes, int n_in,
                              void* d_out, int out_size) {
    const float* x;
    const float* anchors;
    if (in_sizes[0] == 10) { anchors = (const float*)d_in[0]; x = (const float*)d_in[1]; }
    else                   { x = (const float*)d_in[0]; anchors = (const float*)d_in[1]; }
    float* out = (float*)d_out;

    k_decode <<<32, 256>>>(x, anchors, out);
    k_rank   <<<IGROUPS * JC, 256>>>();
    k_scatter<<<32, 256>>>();
    k_nms    <<<NCLS, 512>>>(out);
}

// round 15
// speedup vs baseline: 1.9160x; 1.1107x over previous
#include <cuda_runtime.h>

// ---------------- Problem constants ----------------
#define NBOX 8000          // 5 anchors * 40 * 40
#define HW 40
#define NCLS 20
#define CHSTRIDE (HW*HW)   // 1600 floats between channels
#define STRIDEPX 8.0f      // 320 / 40

#define JC 16
#define CHUNKMAX 500       // ceil(8000/16)
#define IGROUPS 32         // 32*256 = 8192 >= NV

#define MMASK 256          // mask-matrix fast-path capacity (expected M ~ 200)
#define NW 8               // 256/32
#define CAP2 1024          // per-class precomputed-slot capacity (mid path)
#define NMST 1024          // k_nms threads

// ---------------- Scratch (device globals, no allocation) ----------------
__device__ float              d_dec6[NBOX * 6];      // decoded rows, original index order
__device__ unsigned long long d_vkey[NBOX];          // valid keys: (~bits(conf))<<32 | idx
__device__ unsigned char      d_vcode[NBOX];         // valid class
__device__ int                d_nv;                  // valid count accumulator
__device__ int                d_nv2;                 // snapshot (set by k_rank)
__device__ unsigned           d_partial[JC * NBOX];  // packed: rank | cls_rank<<16
__device__ int                d_cnt[NCLS];           // per-class candidate count
__device__ float4             d_cg4 [NCLS * CAP2];   // slot (cls,rc): x1,y1,x2,y2
__device__ float              d_car [NCLS * CAP2];   // slot: area
__device__ int                d_cr  [NCLS * CAP2];   // slot: output row (global rank)
__device__ float              d_crow6[NCLS * CAP2 * 6]; // slot: full output row
__device__ int                d_cand[NCLS * NBOX];   // fallback only: r | orig<<16

// ---------------- K1: decode + valid append + zero output/counters ----------------
__global__ void k_decode(const float* __restrict__ x, const float* __restrict__ anchors,
                         float* __restrict__ out) {
    int tid = threadIdx.x;
    int gid = blockIdx.x * 128 + tid;
    int nthr = gridDim.x * 128;

    // zero output (poisoned before timing) and class counters
    for (int k = gid; k < NBOX * 6; k += nthr) out[k] = 0.0f;
    if (gid < NCLS) d_cnt[gid] = 0;

    int  i   = gid;
    bool inb = (i < NBOX);
    int  ii  = inb ? i : 0;    // clamp for safe loads

    int a   = ii / (HW * HW);
    int rem = ii - a * (HW * HW);
    int gy  = rem / HW;
    int gx  = rem - gy * HW;
    int base = ((a * 25) * HW + gy) * HW + gx;

    // hoist all 25 loads (max MLP)
    float t[5];
#pragma unroll
    for (int k = 0; k < 5; k++) t[k] = x[base + k * CHSTRIDE];
    float cl[NCLS];
#pragma unroll
    for (int c = 0; c < NCLS; c++) cl[c] = x[base + (5 + c) * CHSTRIDE];

    float tx   = 1.0f / (1.0f + expf(-t[0]));
    float ty   = 1.0f / (1.0f + expf(-t[1]));
    float conf = 1.0f / (1.0f + expf(-t[4]));

    float aw = anchors[a * 2 + 0];
    float ah = anchors[a * 2 + 1];

    float bx = (tx + (float)gx) * STRIDEPX;
    float by = (ty + (float)gy) * STRIDEPX;
    float bw = expf(t[2]) * aw * STRIDEPX;
    float bh = expf(t[3]) * ah * STRIDEPX;

    // argmax (strict '>' keeps first occurrence like jnp.argmax)
    float best = cl[0];
    int bc = 0;
#pragma unroll
    for (int c = 1; c < NCLS; c++)
        if (cl[c] > best) { best = cl[c]; bc = c; }

    if (!inb) return;

    d_dec6[i * 6 + 0] = bx;
    d_dec6[i * 6 + 1] = by;
    d_dec6[i * 6 + 2] = bw;
    d_dec6[i * 6 + 3] = bh;
    d_dec6[i * 6 + 4] = conf;
    d_dec6[i * 6 + 5] = (float)bc;

    // valid (conf > 0.5 <=> logit > 0): contiguous append.
    // Slot order nondeterministic; ranks are value-based -> deterministic output.
    if (t[4] > 0.0f) {
        int slot = atomicAdd(&d_nv, 1);
        unsigned u = __float_as_uint(conf);     // conf in (0,1): bits monotone
        d_vkey[slot]  = ((unsigned long long)(~u) << 32) | (unsigned long long)(unsigned)i;
        d_vcode[slot] = (unsigned char)bc;
    }
}

// ---------------- K2: chunked rank over valid boxes (+ snapshot NV) ----------------
__global__ void k_rank() {
    __shared__ unsigned long long sk[CHUNKMAX];
    __shared__ unsigned char     sc[CHUNKMAX];
    int NV = d_nv;
    if (blockIdx.x == 0 && threadIdx.x == 0) d_nv2 = NV;
    int CS = (NV + JC - 1) / JC;
    int g = blockIdx.x / JC;
    int c = blockIdx.x - g * JC;
    int j0 = c * CS;
    int cnt = NV - j0; if (cnt > CS) cnt = CS; if (cnt < 0) cnt = 0;
    for (int t = threadIdx.x; t < cnt; t += 256) {
        sk[t] = d_vkey[j0 + t];
        sc[t] = d_vcode[j0 + t];
    }
    __syncthreads();
    int i = g * 256 + threadIdx.x;
    if (i < NV) {
        unsigned long long my = d_vkey[i];
        unsigned char myc = d_vcode[i];
        unsigned acc = 0;
#pragma unroll 8
        for (int j = 0; j < cnt; j++) {
            bool lt = sk[j] < my;
            acc += lt ? (1u + (((sc[j] == myc) ? 1u : 0u) << 16)) : 0u;
        }
        d_partial[c * NBOX + i] = acc;
    }
}

// ---------------- K2b: scatter -> per-class precomputed slots ----------------
__global__ void k_scatter() {
    int i = blockIdx.x * 256 + threadIdx.x;
    int NV = d_nv;
    if (i >= NV) return;
    unsigned s = 0;
#pragma unroll
    for (int c = 0; c < JC; c++) s += d_partial[c * NBOX + i];
    int r  = (int)(s & 0xffffu);   // global rank among valid == output row
    int rc = (int)(s >> 16);       // class rank (unique within class)
    unsigned long long key = d_vkey[i];
    int orig = (int)(unsigned)(key & 0xffffffffu);
    int cls  = (int)d_vcode[i];
    atomicAdd(&d_cnt[cls], 1);
    if (rc < NBOX) d_cand[cls * NBOX + rc] = r | (orig << 16);  // fallback path
    if (rc < CAP2) {
        float cx = d_dec6[orig * 6 + 0];
        float cy = d_dec6[orig * 6 + 1];
        float w  = d_dec6[orig * 6 + 2];
        float h  = d_dec6[orig * 6 + 3];
        float x1 = cx - 0.5f * w, y1 = cy - 0.5f * h;
        float x2 = cx + 0.5f * w, y2 = cy + 0.5f * h;
        int slot = cls * CAP2 + rc;
        d_cg4[slot] = make_float4(x1, y1, x2, y2);
        d_car[slot] = fabsf((x2 - x1) * (y2 - y1));
        d_cr [slot] = r;
        d_crow6[slot * 6 + 0] = cx;
        d_crow6[slot * 6 + 1] = cy;
        d_crow6[slot * 6 + 2] = w;
        d_crow6[slot * 6 + 3] = h;
        d_crow6[slot * 6 + 4] = d_dec6[orig * 6 + 4];
        d_crow6[slot * 6 + 5] = d_dec6[orig * 6 + 5];
    }
}

// IoU >= 0.5 <=> 2*inter >= union (division-free)
__device__ __forceinline__ bool sup_test4(float4 bi, float ai, float4 bj, float aj) {
    float iw = fmaxf(fminf(bi.z, bj.z) - fmaxf(bi.x, bj.x), 0.0f);
    float ih = fmaxf(fminf(bi.w, bj.w) - fmaxf(bi.y, bj.y), 0.0f);
    float inter = iw * ih;
    float denom = ai + aj - inter + 1e-6f;
    return 2.0f * inter >= denom;
}

// ---------------- K3: per-class NMS (pure: load -> fill -> sweep -> emit) ----------------
__global__ __launch_bounds__(NMST, 1)
void k_nms(float* __restrict__ out) {
    __shared__ float4   sb4[CAP2];              // x1,y1,x2,y2 per slot
    __shared__ float    sar[CAP2];
    __shared__ int      sr[CAP2];
    __shared__ unsigned smask[MMASK * NW];
    __shared__ unsigned srow[NW], skw[NW];

    int c    = blockIdx.x;
    int tid  = threadIdx.x;
    int lane = tid & 31;
    int warp = tid >> 5;

    if (c == 0 && tid == 0) d_nv = 0;   // reset accumulator for next graph replay
    if (tid < NW) srow[tid] = 0;

    int M = d_cnt[c];
    if (M == 0) return;

    if (M <= CAP2) {
        // ---- coalesced load of precomputed per-class slots ----
        for (int t = tid; t < M; t += NMST) {
            sb4[t] = d_cg4[c * CAP2 + t];
            sar[t] = d_car[c * CAP2 + t];
            sr [t] = d_cr [c * CAP2 + t];
        }
        __syncthreads();

        if (M <= MMASK) {
            // ---- ballot mask fill: one warp per row, 32 warps ----
            int nw = (M + 31) >> 5;
            for (int i = warp; i < M; i += 32) {
                float4 bi = sb4[i];
                float  ai = sar[i];
                int wq0 = (i + 1) >> 5;
                unsigned rowany = 0;
                if (lane == 0)
                    for (int q = 0; q < wq0; q++) smask[i * NW + q] = 0;
                for (int wq = wq0; wq < nw; wq++) {
                    int j = (wq << 5) + lane;
                    bool s = (j > i) && (j < M) && sup_test4(bi, ai, sb4[j], sar[j]);
                    unsigned bits = __ballot_sync(0xffffffffu, s);
                    if (lane == 0) smask[i * NW + wq] = bits;
                    rowany |= bits;
                }
                if (lane == 0 && rowany) atomicOr(&srow[i >> 5], 1u << (i & 31));
            }
            __syncthreads();

            // ---- two-level sweep (warp 0): intra-word serial chain, cross-word parallel ----
            if (tid < 32) {
                unsigned kwq = 0;                      // lane q holds keep-word q
                if (lane < NW) {
                    int lo = lane * 32;
                    if (lo < M) {
                        int rem = M - lo;
                        kwq = (rem >= 32) ? 0xffffffffu : ((1u << rem) - 1u);
                    }
                }
                int nwl = (M + 31) >> 5;
                for (int w = 0; w < nwl; w++) {
                    unsigned kwv = __shfl_sync(0xffffffffu, kwq, w);  // word w, uniform
                    unsigned rw  = srow[w];
                    unsigned active = kwv & rw;
                    while (active) {                   // short chain: 1 LDS per step
                        int bb = __ffs(active) - 1;
                        unsigned row_w = smask[(w * 32 + bb) * NW + w];
                        kwv &= ~row_w;                 // mask rows hold only j>i bits
                        active = kwv & rw & (0xfffffffeu << bb);
                    }
                    if (lane == w) kwq = kwv;
                    // bulk-apply word w's surviving suppressors to later words
                    unsigned contrib = kwv & rw;
                    if (lane > w && lane < NW) {
                        unsigned acc = 0, cc = contrib;
                        while (cc) {                   // independent pipelined LDS
                            int bb = __ffs(cc) - 1; cc &= cc - 1;
                            acc |= smask[(w * 32 + bb) * NW + lane];
                        }
                        kwq &= ~acc;
                    }
                }
                if (lane < NW) skw[lane] = kwq;
            }
            __syncthreads();
            // ---- emit kept rows from precomputed row data ----
            for (int t = tid; t < M; t += NMST) {
                if ((skw[t >> 5] >> (t & 31)) & 1u) {
                    int r = sr[t];
                    int slot = c * CAP2 + t;
#pragma unroll
                    for (int q = 0; q < 6; q++) out[6 * r + q] = d_crow6[slot * 6 + q];
                }
            }
        } else {
            // ---- mid path (MMASK < M <= CAP2): pivot loop ----
            unsigned char* skbyte = (unsigned char*)smask;   // 8192B >= CAP2
            for (int t = tid; t < M; t += NMST) skbyte[t] = 1;
            __syncthreads();
            for (int i = 0; i < M - 1; i++) {
                __syncthreads();
                if (!skbyte[i]) continue;
                float4 bi = sb4[i];
                float  ai = sar[i];
                for (int j = i + 1 + tid; j < M; j += NMST) {
                    if (!skbyte[j]) continue;
                    if (sup_test4(bi, ai, sb4[j], sar[j]))
                        skbyte[j] = 0;
                }
            }
            __syncthreads();
            for (int t = tid; t < M; t += NMST) {
                if (skbyte[t]) {
                    int r = sr[t];
                    int slot = c * CAP2 + t;
#pragma unroll
                    for (int q = 0; q < 6; q++) out[6 * r + q] = d_crow6[slot * 6 + q];
                }
            }
        }
    } else {
        // ---- fallback (M > CAP2, never expected): global pivot loop via d_cand ----
        unsigned char* skbyte = (unsigned char*)sb4;     // 16KB >= 8000 >= M
        for (int t = tid; t < M; t += NMST) skbyte[t] = 1;
        __syncthreads();
        for (int i = 0; i < M - 1; i++) {
            __syncthreads();
            if (!skbyte[i]) continue;
            int oi = d_cand[c * NBOX + i] >> 16;
            float cx = d_dec6[oi * 6 + 0], cy = d_dec6[oi * 6 + 1];
            float w  = d_dec6[oi * 6 + 2], h  = d_dec6[oi * 6 + 3];
            float4 bi = make_float4(cx - 0.5f * w, cy - 0.5f * h, cx + 0.5f * w, cy + 0.5f * h);
            float ai = fabsf((bi.z - bi.x) * (bi.w - bi.y));
            for (int j = i + 1 + tid; j < M; j += NMST) {
                if (!skbyte[j]) continue;
                int oj = d_cand[c * NBOX + j] >> 16;
                float cxj = d_dec6[oj * 6 + 0], cyj = d_dec6[oj * 6 + 1];
                float wj  = d_dec6[oj * 6 + 2], hj  = d_dec6[oj * 6 + 3];
                float4 bj = make_float4(cxj - 0.5f * wj, cyj - 0.5f * hj,
                                        cxj + 0.5f * wj, cyj + 0.5f * hj);
                float aj = fabsf((bj.z - bj.x) * (bj.w - bj.y));
                if (sup_test4(bi, ai, bj, aj))
                    skbyte[j] = 0;
            }
        }
        __syncthreads();
        for (int t = tid; t < M; t += NMST) {
            if (skbyte[t]) {
                int p = d_cand[c * NBOX + t];
                int r = p & 0xffff, orig = p >> 16;
#pragma unroll
                for (int q = 0; q < 6; q++) out[6 * r + q] = d_dec6[orig * 6 + q];
            }
        }
    }
}

// ---------------- launch ----------------
extern "C" void kernel_launch(void* const* d_in, const int* in_sizes, int n_in,
                              void* d_out, int out_size) {
    const float* x;
    const float* anchors;
    if (in_sizes[0] == 10) { anchors = (const float*)d_in[0]; x = (const float*)d_in[1]; }
    else                   { x = (const float*)d_in[0]; anchors = (const float*)d_in[1]; }
    float* out = (float*)d_out;

    k_decode <<<63, 128>>>(x, anchors, out);
    k_rank   <<<IGROUPS * JC, 256>>>();
    k_scatter<<<32, 256>>>();
    k_nms    <<<NCLS, NMST>>>(out);
}